// round 7
// baseline (speedup 1.0000x reference)
#include <cuda_runtime.h>
#include <math.h>

#define BS 64
#define NUM_CAMS 6
#define NJ 20
#define NPIX 4096          // 64*64
#define NMAPS (BS*NUM_CAMS*NJ)   // 7680

// Output layout (tuple order, flattened):
//   kp_3d : (BS, NJ, 3)            -> 3840
//   res   : (BS, NJ)               -> 1280
//   kpc   : (BS, NUM_CAMS, NJ, 3)  -> 23040
//   kph   : (BS, NUM_CAMS, NJ, 3)  -> 23040
#define OFF_KP3D 0
#define OFF_RES  (BS*NJ*3)                     // 3840
#define OFF_KPC  (OFF_RES + BS*NJ)             // 5120
#define OFF_KPH  (OFF_KPC + BS*NUM_CAMS*NJ*3)  // 28160

// ---------------------------------------------------------------------------
// Kernel 1: per-(cam-batch, joint) soft-argmax over 64x64 heatmap.
// One block (256 threads) per map; 16 values per thread, single HBM pass.
// ---------------------------------------------------------------------------
__global__ __launch_bounds__(256)
void softargmax_kernel(const float* __restrict__ hm, float* __restrict__ out)
{
    const int map = blockIdx.x;                 // 0..7679
    const float* p = hm + (size_t)map * NPIX;
    const int t = threadIdx.x;

    float vals[16];
    float lmax = -1e30f;
#pragma unroll
    for (int i = 0; i < 4; i++) {
        float4 v = reinterpret_cast<const float4*>(p)[i * 256 + t];
        vals[i*4+0] = v.x * 100.0f;
        vals[i*4+1] = v.y * 100.0f;
        vals[i*4+2] = v.z * 100.0f;
        vals[i*4+3] = v.w * 100.0f;
        lmax = fmaxf(lmax, fmaxf(fmaxf(vals[i*4+0], vals[i*4+1]),
                                 fmaxf(vals[i*4+2], vals[i*4+3])));
    }

    __shared__ float smax[8];
    __shared__ float sacc[3][8];

    const int wid  = t >> 5;
    const int lane = t & 31;

    // block max
#pragma unroll
    for (int o = 16; o > 0; o >>= 1)
        lmax = fmaxf(lmax, __shfl_xor_sync(0xffffffffu, lmax, o));
    if (lane == 0) smax[wid] = lmax;
    __syncthreads();
    float m;
    {
        float v0 = smax[0];
#pragma unroll
        for (int w = 1; w < 8; w++) v0 = fmaxf(v0, smax[w]);
        m = v0;
    }

    // exp + weighted sums. expf(x) == 0 exactly for x < ~-104, so skipping
    // those terms matches the reference bit-for-bit (mod summation order).
    float s = 0.f, sx = 0.f, sy = 0.f;
#pragma unroll
    for (int i = 0; i < 4; i++) {
#pragma unroll
        for (int u = 0; u < 4; u++) {
            float d = vals[i*4+u] - m;
            // warp-uniform skip: most warps have no surviving lane
            if (__ballot_sync(0xffffffffu, d > -104.0f)) {
                if (d > -104.0f) {
                    float e = expf(d);
                    int idx = i * 1024 + t * 4 + u;   // linear pixel index
                    s  += e;
                    sx += e * (float)(idx & 63);      // column (x)
                    sy += e * (float)(idx >> 6);      // row (y)
                }
            }
        }
    }

#pragma unroll
    for (int o = 16; o > 0; o >>= 1) {
        s  += __shfl_xor_sync(0xffffffffu, s,  o);
        sx += __shfl_xor_sync(0xffffffffu, sx, o);
        sy += __shfl_xor_sync(0xffffffffu, sy, o);
    }
    if (lane == 0) { sacc[0][wid] = s; sacc[1][wid] = sx; sacc[2][wid] = sy; }
    __syncthreads();

    if (t == 0) {
        float S = 0.f, X = 0.f, Y = 0.f;
#pragma unroll
        for (int w = 0; w < 8; w++) { S += sacc[0][w]; X += sacc[1][w]; Y += sacc[2][w]; }
        float recS = 1.0f / S;        // == max(softmax) (peak term is exp(0)=1)
        float x = X * recS;
        float y = Y * recS;
        float* kph = out + OFF_KPH + map * 3;
        float* kpc = out + OFF_KPC + map * 3;
        kph[0] = x;        kph[1] = y;        kph[2] = recS;
        kpc[0] = x * 4.0f; kpc[1] = y * 4.0f; kpc[2] = recS;   // 256/64 = 4
    }
}

// ---------------------------------------------------------------------------
// fp64 helpers: float-seeded Newton refinement. Callers guarantee operands
// are range-bounded (well inside float range).
// ---------------------------------------------------------------------------
__device__ __forceinline__ double fast_drcp(double d)
{
    double r = (double)__frcp_rn((float)d);     // ~2^-24
    r = r * (2.0 - d * r);                      // ~2^-48
    r = r * (2.0 - d * r);                      // full fp64
    return r;
}

__device__ __forceinline__ double fast_drsqrt(double d)
{
    double r = (double)__frsqrt_rn((float)d);
    r = r * (1.5 - 0.5 * d * r * r);
    r = r * (1.5 - 0.5 * d * r * r);
    r = r * (1.5 - 0.5 * d * r * r);
    return r;
}

// exact power-of-two ~ 1/sqrt(d): zero rounding perturbation, full fp64 range.
__device__ __forceinline__ double pow2_inv_sqrt_approx(double d)
{
    int hi = __double2hiint(d);
    int e  = ((hi >> 20) & 0x7ff) - 1023;   // floor(log2 d)
    int k  = -(e >> 1);                     // ~ -e/2 (within 1)
    return __hiloint2double((1023 + k) << 20, 0);
}

// ---------------------------------------------------------------------------
// Kernel 2: per-(batch, joint) DLT triangulation.
//   Stage A: fp32 cyclic Jacobi. Rotation uses the CANCELLATION-FREE form
//     t = sign(u) * w / (|u| + sqrt(u^2+w^2)),  c = rsqrt(1+t^2),  s = t*c
//   (algebraically identical to the classic sign(tau)/(|tau|+sqrt(1+tau^2))
//   form that passed in R2 -- multiply num/denom by |w| -- but built from
//   MUFU rsqrt/rcp + Newton, no IEEE div/sqrt subroutines, and NO
//   subtraction of near-equal quantities for small angles).
//   Seed selection: fp64 Rayleigh quotients of all 4 Jacobi columns.
//   Stage B: fp64 inverse iteration x3 (unpivoted LU of PSD AtA, Newton
//            pivot reciprocals), exact pow2 renorm between steps.
// ---------------------------------------------------------------------------
template<int P, int Q>
__device__ __forceinline__ void jrotf(float M[4][4], float V[4][4])
{
    float apq = M[P][Q];
    float u = M[Q][Q] - M[P][P];
    float w = 2.0f * apq;
    float z = fmaf(u, u, w * w);
    if (z > 1e-30f) {                       // also guards w^2-underflow corner
        float app = M[P][P], aqq = M[Q][Q];
        float ir = rsqrtf(z);
        ir = ir * fmaf(-0.5f * z * ir, ir, 1.5f);   // Newton: ~0.5 ulp
        float rho = z * ir;                          // sqrt(z), no cancel
        float den = fabsf(u) + rho;                  // >= |w| > 0
        float tm  = __fdividef(w, den);              // |tm| <= 1
        float t   = (u >= 0.0f) ? tm : -tm;          // tan(theta)
        float h   = fmaf(t, t, 1.0f);                // in [1, 2]
        float ic  = rsqrtf(h);
        ic = ic * fmaf(-0.5f * h * ic, ic, 1.5f);    // Newton
        float c = ic;
        float s = t * c;

        // exact-identity diagonal update (same as the R2 tau-form)
        M[P][P] = fmaf(-t, apq, app);
        M[Q][Q] = fmaf( t, apq, aqq);
        M[P][Q] = 0.0f; M[Q][P] = 0.0f;
#pragma unroll
        for (int r = 0; r < 4; r++) {
            if (r != P && r != Q) {
                float arp = M[r][P], arq = M[r][Q];
                float np = c * arp - s * arq;
                float nq = s * arp + c * arq;
                M[r][P] = np; M[P][r] = np;
                M[r][Q] = nq; M[Q][r] = nq;
            }
        }
#pragma unroll
        for (int r = 0; r < 4; r++) {
            float vp = V[r][P], vq = V[r][Q];
            V[r][P] = c * vp - s * vq;
            V[r][Q] = s * vp + c * vq;
        }
    }
}

__global__ __launch_bounds__(32)
void triangulate_kernel(const float* __restrict__ proj,
                        const float* __restrict__ confid,
                        float* __restrict__ out)
{
    const int tidx = blockIdx.x * blockDim.x + threadIdx.x;
    if (tidx >= BS * NJ) return;
    const int b = tidx / NJ;
    const int j = tidx % NJ;

    // normalized per-camera confidences
    float cf[NUM_CAMS];
    float csum = 0.f;
#pragma unroll
    for (int c = 0; c < NUM_CAMS; c++) {
        cf[c] = confid[(b * NUM_CAMS + c) * NJ + j];
        csum += cf[c];
    }
#pragma unroll
    for (int c = 0; c < NUM_CAMS; c++) cf[c] = cf[c] / csum + 1e-5f;

    // Build A (12x4) in fp32 exactly like the reference
    const float* kpc = out + OFF_KPC;
    float Af[12][4];
#pragma unroll
    for (int c = 0; c < NUM_CAMS; c++) {
        const float* Pc = proj + (b * NUM_CAMS + c) * 12;
        const float px = kpc[((b * NUM_CAMS + c) * NJ + j) * 3 + 0];
        const float py = kpc[((b * NUM_CAMS + c) * NJ + j) * 3 + 1];
#pragma unroll
        for (int k = 0; k < 4; k++) {
            float r2 = Pc[8 + k];
            Af[c*2+0][k] = (r2 * px - Pc[0 + k]) * cf[c];
            Af[c*2+1][k] = (r2 * py - Pc[4 + k]) * cf[c];
        }
    }

    // ---------------- Stage A: fp32 Jacobi on M32 = AtA -------------------
    float M32[4][4], V32[4][4];
#pragma unroll
    for (int k = 0; k < 4; k++)
#pragma unroll
        for (int l = 0; l < 4; l++) { M32[k][l] = 0.0f; V32[k][l] = (k == l) ? 1.0f : 0.0f; }
#pragma unroll
    for (int n = 0; n < 12; n++) {
#pragma unroll
        for (int k = 0; k < 4; k++) {
            float ak = Af[n][k];
#pragma unroll
            for (int l = k; l < 4; l++)
                M32[k][l] = fmaf(ak, Af[n][l], M32[k][l]);
        }
    }
#pragma unroll
    for (int k = 0; k < 4; k++)
#pragma unroll
        for (int l = 0; l < k; l++) M32[k][l] = M32[l][k];

#pragma unroll
    for (int sweep = 0; sweep < 5; sweep++) {
        jrotf<0,1>(M32, V32); jrotf<0,2>(M32, V32); jrotf<0,3>(M32, V32);
        jrotf<1,2>(M32, V32); jrotf<1,3>(M32, V32); jrotf<2,3>(M32, V32);
    }

    // ---------------- fp64 M = AtA ----------------------------------------
    double M[4][4];
#pragma unroll
    for (int k = 0; k < 4; k++)
#pragma unroll
        for (int l = 0; l < 4; l++) M[k][l] = 0.0;
#pragma unroll
    for (int n = 0; n < 12; n++) {
#pragma unroll
        for (int k = 0; k < 4; k++) {
            double ak = (double)Af[n][k];
#pragma unroll
            for (int l = k; l < 4; l++)
                M[k][l] = fma(ak, (double)Af[n][l], M[k][l]);
        }
    }
#pragma unroll
    for (int k = 0; k < 4; k++)
#pragma unroll
        for (int l = 0; l < k; l++) M[k][l] = M[l][k];

    // -------- Seed selection: fp64 Rayleigh quotient per Jacobi column ----
    double q[4];
#pragma unroll
    for (int r = 0; r < 4; r++) {
        double v0 = (double)V32[0][r], v1 = (double)V32[1][r];
        double v2 = (double)V32[2][r], v3 = (double)V32[3][r];
        double y0 = fma(M[0][0], v0, fma(M[0][1], v1, fma(M[0][2], v2, M[0][3] * v3)));
        double y1 = fma(M[1][0], v0, fma(M[1][1], v1, fma(M[1][2], v2, M[1][3] * v3)));
        double y2 = fma(M[2][0], v0, fma(M[2][1], v1, fma(M[2][2], v2, M[2][3] * v3)));
        double y3 = fma(M[3][0], v0, fma(M[3][1], v1, fma(M[3][2], v2, M[3][3] * v3)));
        q[r] = fma(v0, y0, fma(v1, y1, fma(v2, y2, v3 * y3)));
    }
    int mi = 0; double qm = q[0];
    if (q[1] < qm) { qm = q[1]; mi = 1; }
    if (q[2] < qm) { qm = q[2]; mi = 2; }
    if (q[3] < qm) { qm = q[3]; mi = 3; }

    double x[4];
#pragma unroll
    for (int r = 0; r < 4; r++) {
        float vr = (mi == 0) ? V32[r][0] : (mi == 1) ? V32[r][1]
                 : (mi == 2) ? V32[r][2] : V32[r][3];
        x[r] = (double)vr;
    }

    // ---------------- Stage B: LU (no pivot, PSD), 3 solves ---------------
    double rcp[4];
#pragma unroll
    for (int k = 0; k < 4; k++) {
        rcp[k] = fast_drcp(M[k][k]);
#pragma unroll
        for (int i = k + 1; i < 4; i++) {
            double l = M[i][k] * rcp[k];
            M[i][k] = l;
#pragma unroll
            for (int jj = k + 1; jj < 4; jj++)
                M[i][jj] = fma(-l, M[k][jj], M[i][jj]);
        }
    }

    // three inverse-iteration steps with exact power-of-two renormalization
#pragma unroll
    for (int it = 0; it < 3; it++) {
        // forward: L y = x (unit diag)
        double y0 = x[0];
        double y1 = fma(-M[1][0], y0, x[1]);
        double y2 = fma(-M[2][1], y1, fma(-M[2][0], y0, x[2]));
        double y3 = fma(-M[3][2], y2, fma(-M[3][1], y1, fma(-M[3][0], y0, x[3])));
        // backward: U x = y
        double x3 = y3 * rcp[3];
        double x2 = fma(-M[2][3], x3, y2) * rcp[2];
        double x1 = fma(-M[1][3], x3, fma(-M[1][2], x2, y1)) * rcp[1];
        double x0 = fma(-M[0][3], x3, fma(-M[0][2], x2, fma(-M[0][1], x1, y0))) * rcp[0];
        double n2 = fma(x0, x0, fma(x1, x1, fma(x2, x2, x3 * x3)));
        double sc = pow2_inv_sqrt_approx(n2);   // keeps ||x|| in ~[0.5, 2]
        x[0] = x0 * sc; x[1] = x1 * sc; x[2] = x2 * sc; x[3] = x3 * sc;
    }

    // exact unit 2-norm (operand is O(1) -- float-seeded rsqrt is safe)
    double nrm2 = fma(x[0], x[0], fma(x[1], x[1], fma(x[2], x[2], x[3] * x[3])));
    double inrm = fast_drsqrt(nrm2);
    double v[4] = { x[0] * inrm, x[1] * inrm, x[2] * inrm, x[3] * inrm };

    // kp_3d = homo[:3]/homo[3]; homo = -v, sign cancels
    double inv = fast_drcp(v[3]);
    float* kp3 = out + OFF_KP3D + tidx * 3;
    kp3[0] = (float)(v[0] * inv);
    kp3[1] = (float)(v[1] * inv);
    kp3[2] = (float)(v[2] * inv);

    // res = sum_n |A[n,:] . homo|  (abs -> sign-invariant)
    double acc = 0.0;
#pragma unroll
    for (int n = 0; n < 12; n++) {
        double dsum = fma((double)Af[n][0], v[0],
                      fma((double)Af[n][1], v[1],
                      fma((double)Af[n][2], v[2], (double)Af[n][3] * v[3])));
        acc += fabs(dsum);
    }
    out[OFF_RES + tidx] = (float)acc;
}

// ---------------------------------------------------------------------------
extern "C" void kernel_launch(void* const* d_in, const int* in_sizes, int n_in,
                              void* d_out, int out_size)
{
    const float* heatmap = (const float*)d_in[0];  // (384, 20, 64, 64)
    const float* proj    = (const float*)d_in[1];  // (64, 6, 3, 4)
    const float* confid  = (const float*)d_in[2];  // (384, 20)
    float* out = (float*)d_out;                    // 51200 floats

    softargmax_kernel<<<NMAPS, 256>>>(heatmap, out);
    triangulate_kernel<<<(BS * NJ + 31) / 32, 32>>>(proj, confid, out);
}

// round 8
// speedup vs baseline: 1.1352x; 1.1352x over previous
#include <cuda_runtime.h>
#include <math.h>

#define BS 64
#define NUM_CAMS 6
#define NJ 20
#define NPIX 4096          // 64*64
#define NMAPS (BS*NUM_CAMS*NJ)   // 7680

// Output layout (tuple order, flattened):
//   kp_3d : (BS, NJ, 3)            -> 3840
//   res   : (BS, NJ)               -> 1280
//   kpc   : (BS, NUM_CAMS, NJ, 3)  -> 23040
//   kph   : (BS, NUM_CAMS, NJ, 3)  -> 23040
#define OFF_KP3D 0
#define OFF_RES  (BS*NJ*3)                     // 3840
#define OFF_KPC  (OFF_RES + BS*NJ)             // 5120
#define OFF_KPH  (OFF_KPC + BS*NUM_CAMS*NJ*3)  // 28160

// ---------------------------------------------------------------------------
// Kernel 1: per-(cam-batch, joint) soft-argmax over 64x64 heatmap.
// ---------------------------------------------------------------------------
__global__ __launch_bounds__(256)
void softargmax_kernel(const float* __restrict__ hm, float* __restrict__ out)
{
    const int map = blockIdx.x;                 // 0..7679
    const float* p = hm + (size_t)map * NPIX;
    const int t = threadIdx.x;

    float vals[16];
    float lmax = -1e30f;
#pragma unroll
    for (int i = 0; i < 4; i++) {
        float4 v = __ldcs(reinterpret_cast<const float4*>(p) + i * 256 + t);
        vals[i*4+0] = v.x * 100.0f;
        vals[i*4+1] = v.y * 100.0f;
        vals[i*4+2] = v.z * 100.0f;
        vals[i*4+3] = v.w * 100.0f;
        lmax = fmaxf(lmax, fmaxf(fmaxf(vals[i*4+0], vals[i*4+1]),
                                 fmaxf(vals[i*4+2], vals[i*4+3])));
    }

    __shared__ float smax[8];
    __shared__ float sacc[3][8];

    const int wid  = t >> 5;
    const int lane = t & 31;

#pragma unroll
    for (int o = 16; o > 0; o >>= 1)
        lmax = fmaxf(lmax, __shfl_xor_sync(0xffffffffu, lmax, o));
    if (lane == 0) smax[wid] = lmax;
    __syncthreads();
    float m;
    {
        float v0 = smax[0];
#pragma unroll
        for (int w = 1; w < 8; w++) v0 = fmaxf(v0, smax[w]);
        m = v0;
    }

    // exp + weighted sums. expf(x) == 0 exactly for x < ~-104, so skipping
    // those terms matches the reference bit-for-bit (mod summation order).
    float s = 0.f, sx = 0.f, sy = 0.f;
#pragma unroll
    for (int i = 0; i < 4; i++) {
#pragma unroll
        for (int u = 0; u < 4; u++) {
            float d = vals[i*4+u] - m;
            if (__ballot_sync(0xffffffffu, d > -104.0f)) {
                if (d > -104.0f) {
                    float e = expf(d);
                    int idx = i * 1024 + t * 4 + u;   // linear pixel index
                    s  += e;
                    sx += e * (float)(idx & 63);      // column (x)
                    sy += e * (float)(idx >> 6);      // row (y)
                }
            }
        }
    }

#pragma unroll
    for (int o = 16; o > 0; o >>= 1) {
        s  += __shfl_xor_sync(0xffffffffu, s,  o);
        sx += __shfl_xor_sync(0xffffffffu, sx, o);
        sy += __shfl_xor_sync(0xffffffffu, sy, o);
    }
    if (lane == 0) { sacc[0][wid] = s; sacc[1][wid] = sx; sacc[2][wid] = sy; }
    __syncthreads();

    if (t == 0) {
        float S = 0.f, X = 0.f, Y = 0.f;
#pragma unroll
        for (int w = 0; w < 8; w++) { S += sacc[0][w]; X += sacc[1][w]; Y += sacc[2][w]; }
        float recS = 1.0f / S;        // == max(softmax) (peak term is exp(0)=1)
        float x = X * recS;
        float y = Y * recS;
        float* kph = out + OFF_KPH + map * 3;
        float* kpc = out + OFF_KPC + map * 3;
        kph[0] = x;        kph[1] = y;        kph[2] = recS;
        kpc[0] = x * 4.0f; kpc[1] = y * 4.0f; kpc[2] = recS;   // 256/64 = 4
    }
}

// ---------------------------------------------------------------------------
// fp64 helpers: float-seeded Newton refinement. Callers guarantee operands
// are range-bounded (well inside float range).
// ---------------------------------------------------------------------------
__device__ __forceinline__ double fast_drcp(double d)
{
    double r = (double)__frcp_rn((float)d);     // ~2^-24
    r = r * (2.0 - d * r);                      // ~2^-48
    r = r * (2.0 - d * r);                      // full fp64
    return r;
}

__device__ __forceinline__ double fast_drsqrt(double d)
{
    double r = (double)__frsqrt_rn((float)d);
    r = r * (1.5 - 0.5 * d * r * r);
    r = r * (1.5 - 0.5 * d * r * r);
    r = r * (1.5 - 0.5 * d * r * r);
    return r;
}

// exact power-of-two ~ 1/sqrt(d): zero rounding perturbation, full fp64 range.
__device__ __forceinline__ double pow2_inv_sqrt_approx(double d)
{
    int hi = __double2hiint(d);
    int e  = ((hi >> 20) & 0x7ff) - 1023;   // floor(log2 d)
    int k  = -(e >> 1);                     // ~ -e/2 (within 1)
    return __hiloint2double((1023 + k) << 20, 0);
}

// ---------------------------------------------------------------------------
// Kernel 2: per-(batch, joint) DLT triangulation.
//   fp32 cyclic Jacobi (cancellation-free t-form, raw MUFU rsqrt) -> seed,
//   selected by fp32 diagonal argmin (R2-proven with these rotations).
//   fp64: AtA build (overlaps Jacobi on the fp64 pipe), unpivoted LU with
//   Newton pivot reciprocals, 2 inverse-iteration solves (pow2 renorm after
//   the first to keep the final norm inside float range).
// ---------------------------------------------------------------------------
template<int P, int Q>
__device__ __forceinline__ void jrotf(float M[4][4], float V[4][4])
{
    float apq = M[P][Q];
    float u = M[Q][Q] - M[P][P];
    float w = 2.0f * apq;
    float z = fmaf(u, u, w * w);
    if (z > 1e-30f) {                       // also guards w^2-underflow corner
        float app = M[P][P], aqq = M[Q][Q];
        float rho = z * rsqrtf(z);                   // sqrt(z), no cancel
        float den = fabsf(u) + rho;                  // >= |w| > 0
        float tm  = __fdividef(w, den);              // |tm| <= 1
        float t   = (u >= 0.0f) ? tm : -tm;          // tan(theta)
        float c   = rsqrtf(fmaf(t, t, 1.0f));        // cos(theta)
        float s   = t * c;

        M[P][P] = fmaf(-t, apq, app);
        M[Q][Q] = fmaf( t, apq, aqq);
        M[P][Q] = 0.0f; M[Q][P] = 0.0f;
#pragma unroll
        for (int r = 0; r < 4; r++) {
            if (r != P && r != Q) {
                float arp = M[r][P], arq = M[r][Q];
                float np = c * arp - s * arq;
                float nq = s * arp + c * arq;
                M[r][P] = np; M[P][r] = np;
                M[r][Q] = nq; M[Q][r] = nq;
            }
        }
#pragma unroll
        for (int r = 0; r < 4; r++) {
            float vp = V[r][P], vq = V[r][Q];
            V[r][P] = c * vp - s * vq;
            V[r][Q] = s * vp + c * vq;
        }
    }
}

__global__ __launch_bounds__(32)
void triangulate_kernel(const float* __restrict__ proj,
                        const float* __restrict__ confid,
                        float* __restrict__ out)
{
    const int tidx = blockIdx.x * blockDim.x + threadIdx.x;
    if (tidx >= BS * NJ) return;
    const int b = tidx / NJ;
    const int j = tidx % NJ;

    // normalized per-camera confidences
    float cf[NUM_CAMS];
    float csum = 0.f;
#pragma unroll
    for (int c = 0; c < NUM_CAMS; c++) {
        cf[c] = confid[(b * NUM_CAMS + c) * NJ + j];
        csum += cf[c];
    }
#pragma unroll
    for (int c = 0; c < NUM_CAMS; c++) cf[c] = cf[c] / csum + 1e-5f;

    // Build A (12x4) in fp32 exactly like the reference
    const float* kpc = out + OFF_KPC;
    float Af[12][4];
#pragma unroll
    for (int c = 0; c < NUM_CAMS; c++) {
        const float* Pc = proj + (b * NUM_CAMS + c) * 12;
        const float px = kpc[((b * NUM_CAMS + c) * NJ + j) * 3 + 0];
        const float py = kpc[((b * NUM_CAMS + c) * NJ + j) * 3 + 1];
#pragma unroll
        for (int k = 0; k < 4; k++) {
            float r2 = Pc[8 + k];
            Af[c*2+0][k] = (r2 * px - Pc[0 + k]) * cf[c];
            Af[c*2+1][k] = (r2 * py - Pc[4 + k]) * cf[c];
        }
    }

    // ---------------- fp64 M = AtA (fp64 pipe; overlaps Jacobi below) -----
    double M[4][4];
#pragma unroll
    for (int k = 0; k < 4; k++)
#pragma unroll
        for (int l = 0; l < 4; l++) M[k][l] = 0.0;
#pragma unroll
    for (int n = 0; n < 12; n++) {
#pragma unroll
        for (int k = 0; k < 4; k++) {
            double ak = (double)Af[n][k];
#pragma unroll
            for (int l = k; l < 4; l++)
                M[k][l] = fma(ak, (double)Af[n][l], M[k][l]);
        }
    }
#pragma unroll
    for (int k = 0; k < 4; k++)
#pragma unroll
        for (int l = 0; l < k; l++) M[k][l] = M[l][k];

    // ---------------- fp32 Jacobi on M32 = AtA (fp32/MUFU pipes) ----------
    float M32[4][4], V32[4][4];
#pragma unroll
    for (int k = 0; k < 4; k++)
#pragma unroll
        for (int l = 0; l < 4; l++) { M32[k][l] = 0.0f; V32[k][l] = (k == l) ? 1.0f : 0.0f; }
#pragma unroll
    for (int n = 0; n < 12; n++) {
#pragma unroll
        for (int k = 0; k < 4; k++) {
            float ak = Af[n][k];
#pragma unroll
            for (int l = k; l < 4; l++)
                M32[k][l] = fmaf(ak, Af[n][l], M32[k][l]);
        }
    }
#pragma unroll
    for (int k = 0; k < 4; k++)
#pragma unroll
        for (int l = 0; l < k; l++) M32[k][l] = M32[l][k];

#pragma unroll
    for (int sweep = 0; sweep < 5; sweep++) {
        jrotf<0,1>(M32, V32); jrotf<0,2>(M32, V32); jrotf<0,3>(M32, V32);
        jrotf<1,2>(M32, V32); jrotf<1,3>(M32, V32); jrotf<2,3>(M32, V32);
    }

    // seed selection: fp32 diagonal argmin (R2-proven with these rotations)
    int mi = 0; float dmf = M32[0][0];
    if (M32[1][1] < dmf) { dmf = M32[1][1]; mi = 1; }
    if (M32[2][2] < dmf) { dmf = M32[2][2]; mi = 2; }
    if (M32[3][3] < dmf) { dmf = M32[3][3]; mi = 3; }

    double x[4];
#pragma unroll
    for (int r = 0; r < 4; r++) {
        float vr = (mi == 0) ? V32[r][0] : (mi == 1) ? V32[r][1]
                 : (mi == 2) ? V32[r][2] : V32[r][3];
        x[r] = (double)vr;
    }

    // ---------------- LU (no pivot, PSD), Newton pivot reciprocals --------
    double rcp[4];
#pragma unroll
    for (int k = 0; k < 4; k++) {
        rcp[k] = fast_drcp(M[k][k]);
#pragma unroll
        for (int i = k + 1; i < 4; i++) {
            double l = M[i][k] * rcp[k];
            M[i][k] = l;
#pragma unroll
            for (int jj = k + 1; jj < 4; jj++)
                M[i][jj] = fma(-l, M[k][jj], M[i][jj]);
        }
    }

    // two inverse-iteration steps; exact pow2 renorm after the first keeps
    // the final squared norm inside float range (needed by fast_drsqrt).
#pragma unroll
    for (int it = 0; it < 2; it++) {
        double y0 = x[0];
        double y1 = fma(-M[1][0], y0, x[1]);
        double y2 = fma(-M[2][1], y1, fma(-M[2][0], y0, x[2]));
        double y3 = fma(-M[3][2], y2, fma(-M[3][1], y1, fma(-M[3][0], y0, x[3])));
        double x3 = y3 * rcp[3];
        double x2 = fma(-M[2][3], x3, y2) * rcp[2];
        double x1 = fma(-M[1][3], x3, fma(-M[1][2], x2, y1)) * rcp[1];
        double x0 = fma(-M[0][3], x3, fma(-M[0][2], x2, fma(-M[0][1], x1, y0))) * rcp[0];
        if (it == 0) {
            double n2 = fma(x0, x0, fma(x1, x1, fma(x2, x2, x3 * x3)));
            double sc = pow2_inv_sqrt_approx(n2);   // ||x|| -> ~[0.5, 2]
            x[0] = x0 * sc; x[1] = x1 * sc; x[2] = x2 * sc; x[3] = x3 * sc;
        } else {
            x[0] = x0; x[1] = x1; x[2] = x2; x[3] = x3;
        }
    }

    // exact unit 2-norm (nrm2 <= ~1e26 after renorm: float-safe)
    double nrm2 = fma(x[0], x[0], fma(x[1], x[1], fma(x[2], x[2], x[3] * x[3])));
    double inrm = fast_drsqrt(nrm2);
    double v[4] = { x[0] * inrm, x[1] * inrm, x[2] * inrm, x[3] * inrm };

    // kp_3d = homo[:3]/homo[3]; homo = -v, sign cancels
    double inv = fast_drcp(v[3]);
    float* kp3 = out + OFF_KP3D + tidx * 3;
    kp3[0] = (float)(v[0] * inv);
    kp3[1] = (float)(v[1] * inv);
    kp3[2] = (float)(v[2] * inv);

    // res = sum_n |A[n,:] . homo|  (abs -> sign-invariant)
    double acc = 0.0;
#pragma unroll
    for (int n = 0; n < 12; n++) {
        double dsum = fma((double)Af[n][0], v[0],
                      fma((double)Af[n][1], v[1],
                      fma((double)Af[n][2], v[2], (double)Af[n][3] * v[3])));
        acc += fabs(dsum);
    }
    out[OFF_RES + tidx] = (float)acc;
}

// ---------------------------------------------------------------------------
extern "C" void kernel_launch(void* const* d_in, const int* in_sizes, int n_in,
                              void* d_out, int out_size)
{
    const float* heatmap = (const float*)d_in[0];  // (384, 20, 64, 64)
    const float* proj    = (const float*)d_in[1];  // (64, 6, 3, 4)
    const float* confid  = (const float*)d_in[2];  // (384, 20)
    float* out = (float*)d_out;                    // 51200 floats

    softargmax_kernel<<<NMAPS, 256>>>(heatmap, out);
    triangulate_kernel<<<(BS * NJ + 31) / 32, 32>>>(proj, confid, out);
}

// round 9
// speedup vs baseline: 1.1535x; 1.0162x over previous
#include <cuda_runtime.h>
#include <math.h>

#define BS 64
#define NUM_CAMS 6
#define NJ 20
#define NPIX 4096          // 64*64
#define NMAPS (BS*NUM_CAMS*NJ)   // 7680

// Output layout (tuple order, flattened):
//   kp_3d : (BS, NJ, 3)            -> 3840
//   res   : (BS, NJ)               -> 1280
//   kpc   : (BS, NUM_CAMS, NJ, 3)  -> 23040
//   kph   : (BS, NUM_CAMS, NJ, 3)  -> 23040
#define OFF_KP3D 0
#define OFF_RES  (BS*NJ*3)                     // 3840
#define OFF_KPC  (OFF_RES + BS*NJ)             // 5120
#define OFF_KPH  (OFF_KPC + BS*NUM_CAMS*NJ*3)  // 28160

// ---------------------------------------------------------------------------
// Kernel 1: per-(cam-batch, joint) soft-argmax over 64x64 heatmap.
// ---------------------------------------------------------------------------
__global__ __launch_bounds__(256)
void softargmax_kernel(const float* __restrict__ hm, float* __restrict__ out)
{
    const int map = blockIdx.x;                 // 0..7679
    const float* p = hm + (size_t)map * NPIX;
    const int t = threadIdx.x;

    float vals[16];
    float lmax = -1e30f;
#pragma unroll
    for (int i = 0; i < 4; i++) {
        float4 v = __ldcs(reinterpret_cast<const float4*>(p) + i * 256 + t);
        vals[i*4+0] = v.x * 100.0f;
        vals[i*4+1] = v.y * 100.0f;
        vals[i*4+2] = v.z * 100.0f;
        vals[i*4+3] = v.w * 100.0f;
        lmax = fmaxf(lmax, fmaxf(fmaxf(vals[i*4+0], vals[i*4+1]),
                                 fmaxf(vals[i*4+2], vals[i*4+3])));
    }

    __shared__ float smax[8];
    __shared__ float sacc[3][8];

    const int wid  = t >> 5;
    const int lane = t & 31;

#pragma unroll
    for (int o = 16; o > 0; o >>= 1)
        lmax = fmaxf(lmax, __shfl_xor_sync(0xffffffffu, lmax, o));
    if (lane == 0) smax[wid] = lmax;
    __syncthreads();
    float m;
    {
        float v0 = smax[0];
#pragma unroll
        for (int w = 1; w < 8; w++) v0 = fmaxf(v0, smax[w]);
        m = v0;
    }

    // exp + weighted sums. expf(x) == 0 exactly for x < ~-104, so skipping
    // those terms matches the reference bit-for-bit (mod summation order).
    float s = 0.f, sx = 0.f, sy = 0.f;
#pragma unroll
    for (int i = 0; i < 4; i++) {
#pragma unroll
        for (int u = 0; u < 4; u++) {
            float d = vals[i*4+u] - m;
            if (__ballot_sync(0xffffffffu, d > -104.0f)) {
                if (d > -104.0f) {
                    float e = expf(d);
                    int idx = i * 1024 + t * 4 + u;   // linear pixel index
                    s  += e;
                    sx += e * (float)(idx & 63);      // column (x)
                    sy += e * (float)(idx >> 6);      // row (y)
                }
            }
        }
    }

#pragma unroll
    for (int o = 16; o > 0; o >>= 1) {
        s  += __shfl_xor_sync(0xffffffffu, s,  o);
        sx += __shfl_xor_sync(0xffffffffu, sx, o);
        sy += __shfl_xor_sync(0xffffffffu, sy, o);
    }
    if (lane == 0) { sacc[0][wid] = s; sacc[1][wid] = sx; sacc[2][wid] = sy; }
    __syncthreads();

    if (t == 0) {
        float S = 0.f, X = 0.f, Y = 0.f;
#pragma unroll
        for (int w = 0; w < 8; w++) { S += sacc[0][w]; X += sacc[1][w]; Y += sacc[2][w]; }
        float recS = 1.0f / S;        // == max(softmax) (peak term is exp(0)=1)
        float x = X * recS;
        float y = Y * recS;
        float* kph = out + OFF_KPH + map * 3;
        float* kpc = out + OFF_KPC + map * 3;
        kph[0] = x;        kph[1] = y;        kph[2] = recS;
        kpc[0] = x * 4.0f; kpc[1] = y * 4.0f; kpc[2] = recS;   // 256/64 = 4
    }
}

// ---------------------------------------------------------------------------
// fp64 helpers (float-seeded Newton; operands guaranteed float-range by callers)
// ---------------------------------------------------------------------------
__device__ __forceinline__ double fast_drcp(double d)        // ~2^-48 rel
{
    double r = (double)__frcp_rn((float)d);
    r = r * (2.0 - d * r);
    return r;
}

__device__ __forceinline__ double fast_drsqrt(double d)      // ~2^-48 rel
{
    double r = (double)__frsqrt_rn((float)d);
    r = r * (1.5 - 0.5 * d * r * r);
    r = r * (1.5 - 0.5 * d * r * r);
    return r;
}

// exact power-of-two ~ 1/sqrt(d): zero rounding perturbation, full fp64 range.
__device__ __forceinline__ double pow2_inv_sqrt_approx(double d)
{
    int hi = __double2hiint(d);
    int e  = ((hi >> 20) & 0x7ff) - 1023;   // floor(log2 d)
    int k  = -(e >> 1);                     // ~ -e/2 (within 1)
    return __hiloint2double((1023 + k) << 20, 0);
}

// ---------------------------------------------------------------------------
// Kernel 2: per-(batch, joint) DLT triangulation.
//   fp32 cyclic Jacobi (cancellation-free t-form) -> seed (diag argmin).
//   Polish: TWO adjugate applications  x <- adj(M).x  (M PSD => direction
//   identical to inverse iteration; no divisions; cofactors are independent
//   -> dependency depth ~500 cyc vs ~3.6k for LU). Exact pow2 renorm after
//   each application keeps everything float-seed safe.
// ---------------------------------------------------------------------------
template<int P, int Q>
__device__ __forceinline__ void jrotf(float M[4][4], float V[4][4])
{
    float apq = M[P][Q];
    float u = M[Q][Q] - M[P][P];
    float w = 2.0f * apq;
    float z = fmaf(u, u, w * w);
    if (z > 1e-30f) {                       // also guards w^2-underflow corner
        float app = M[P][P], aqq = M[Q][Q];
        float rho = z * rsqrtf(z);                   // sqrt(z), no cancel
        float den = fabsf(u) + rho;                  // >= |w| > 0
        float tm  = __fdividef(w, den);              // |tm| <= 1
        float t   = (u >= 0.0f) ? tm : -tm;          // tan(theta)
        float c   = rsqrtf(fmaf(t, t, 1.0f));        // cos(theta)
        float s   = t * c;

        M[P][P] = fmaf(-t, apq, app);
        M[Q][Q] = fmaf( t, apq, aqq);
        M[P][Q] = 0.0f; M[Q][P] = 0.0f;
#pragma unroll
        for (int r = 0; r < 4; r++) {
            if (r != P && r != Q) {
                float arp = M[r][P], arq = M[r][Q];
                float np = c * arp - s * arq;
                float nq = s * arp + c * arq;
                M[r][P] = np; M[P][r] = np;
                M[r][Q] = nq; M[Q][r] = nq;
            }
        }
#pragma unroll
        for (int r = 0; r < 4; r++) {
            float vp = V[r][P], vq = V[r][Q];
            V[r][P] = c * vp - s * vq;
            V[r][Q] = s * vp + c * vq;
        }
    }
}

__global__ __launch_bounds__(32)
void triangulate_kernel(const float* __restrict__ proj,
                        const float* __restrict__ confid,
                        float* __restrict__ out)
{
    const int tidx = blockIdx.x * blockDim.x + threadIdx.x;
    if (tidx >= BS * NJ) return;
    const int b = tidx / NJ;
    const int j = tidx % NJ;

    // normalized per-camera confidences
    float cf[NUM_CAMS];
    float csum = 0.f;
#pragma unroll
    for (int c = 0; c < NUM_CAMS; c++) {
        cf[c] = confid[(b * NUM_CAMS + c) * NJ + j];
        csum += cf[c];
    }
#pragma unroll
    for (int c = 0; c < NUM_CAMS; c++) cf[c] = cf[c] / csum + 1e-5f;

    // Build A (12x4) in fp32 exactly like the reference
    const float* kpc = out + OFF_KPC;
    float Af[12][4];
#pragma unroll
    for (int c = 0; c < NUM_CAMS; c++) {
        const float* Pc = proj + (b * NUM_CAMS + c) * 12;
        const float px = kpc[((b * NUM_CAMS + c) * NJ + j) * 3 + 0];
        const float py = kpc[((b * NUM_CAMS + c) * NJ + j) * 3 + 1];
#pragma unroll
        for (int k = 0; k < 4; k++) {
            float r2 = Pc[8 + k];
            Af[c*2+0][k] = (r2 * px - Pc[0 + k]) * cf[c];
            Af[c*2+1][k] = (r2 * py - Pc[4 + k]) * cf[c];
        }
    }

    // ---------------- fp64 M = AtA (fp64 pipe; overlaps Jacobi below) -----
    double M[4][4];
#pragma unroll
    for (int k = 0; k < 4; k++)
#pragma unroll
        for (int l = 0; l < 4; l++) M[k][l] = 0.0;
#pragma unroll
    for (int n = 0; n < 12; n++) {
#pragma unroll
        for (int k = 0; k < 4; k++) {
            double ak = (double)Af[n][k];
#pragma unroll
            for (int l = k; l < 4; l++)
                M[k][l] = fma(ak, (double)Af[n][l], M[k][l]);
        }
    }
#pragma unroll
    for (int k = 0; k < 4; k++)
#pragma unroll
        for (int l = 0; l < k; l++) M[k][l] = M[l][k];

    // ---------------- fp32 Jacobi on M32 = AtA (fp32/MUFU pipes) ----------
    float M32[4][4], V32[4][4];
#pragma unroll
    for (int k = 0; k < 4; k++)
#pragma unroll
        for (int l = 0; l < 4; l++) { M32[k][l] = 0.0f; V32[k][l] = (k == l) ? 1.0f : 0.0f; }
#pragma unroll
    for (int n = 0; n < 12; n++) {
#pragma unroll
        for (int k = 0; k < 4; k++) {
            float ak = Af[n][k];
#pragma unroll
            for (int l = k; l < 4; l++)
                M32[k][l] = fmaf(ak, Af[n][l], M32[k][l]);
        }
    }
#pragma unroll
    for (int k = 0; k < 4; k++)
#pragma unroll
        for (int l = 0; l < k; l++) M32[k][l] = M32[l][k];

#pragma unroll
    for (int sweep = 0; sweep < 5; sweep++) {
        jrotf<0,1>(M32, V32); jrotf<0,2>(M32, V32); jrotf<0,3>(M32, V32);
        jrotf<1,2>(M32, V32); jrotf<1,3>(M32, V32); jrotf<2,3>(M32, V32);
    }

    // seed selection: fp32 diagonal argmin (R2-proven with these rotations)
    int mi = 0; float dmf = M32[0][0];
    if (M32[1][1] < dmf) { dmf = M32[1][1]; mi = 1; }
    if (M32[2][2] < dmf) { dmf = M32[2][2]; mi = 2; }
    if (M32[3][3] < dmf) { dmf = M32[3][3]; mi = 3; }

    double x[4];
#pragma unroll
    for (int r = 0; r < 4; r++) {
        float vr = (mi == 0) ? V32[r][0] : (mi == 1) ? V32[r][1]
                 : (mi == 2) ? V32[r][2] : V32[r][3];
        x[r] = (double)vr;
    }

    // ---------------- adjugate of symmetric 4x4 M (MESA 2x2-subdet form) --
    // 12 independent 2x2 sub-determinants (depth 2), then 10 independent
    // cofactors (depth 3). No divisions; det(M) > 0 (PSD) so adj.x keeps the
    // inverse-iteration direction.
    double s0 = fma(M[0][0], M[1][1], -M[1][0] * M[0][1]);
    double s1 = fma(M[0][0], M[1][2], -M[1][0] * M[0][2]);
    double s2 = fma(M[0][0], M[1][3], -M[1][0] * M[0][3]);
    double s3 = fma(M[0][1], M[1][2], -M[1][1] * M[0][2]);
    double s4 = fma(M[0][1], M[1][3], -M[1][1] * M[0][3]);
    double s5 = fma(M[0][2], M[1][3], -M[1][2] * M[0][3]);
    double c5 = fma(M[2][2], M[3][3], -M[3][2] * M[2][3]);
    double c4 = fma(M[2][1], M[3][3], -M[3][1] * M[2][3]);
    double c3 = fma(M[2][1], M[3][2], -M[3][1] * M[2][2]);
    double c2 = fma(M[2][0], M[3][3], -M[3][0] * M[2][3]);
    double c1 = fma(M[2][0], M[3][2], -M[3][0] * M[2][2]);
    double c0 = fma(M[2][0], M[3][1], -M[3][0] * M[2][1]);

    double J00 = fma( M[1][1], c5, fma(-M[1][2], c4,  M[1][3] * c3));
    double J01 = fma(-M[0][1], c5, fma( M[0][2], c4, -M[0][3] * c3));
    double J02 = fma( M[3][1], s5, fma(-M[3][2], s4,  M[3][3] * s3));
    double J03 = fma(-M[2][1], s5, fma( M[2][2], s4, -M[2][3] * s3));
    double J11 = fma( M[0][0], c5, fma(-M[0][2], c2,  M[0][3] * c1));
    double J12 = fma(-M[3][0], s5, fma( M[3][2], s2, -M[3][3] * s1));
    double J13 = fma( M[2][0], s5, fma(-M[2][2], s2,  M[2][3] * s1));
    double J22 = fma( M[3][0], s4, fma(-M[3][1], s2,  M[3][3] * s0));
    double J23 = fma(-M[2][0], s4, fma( M[2][1], s2, -M[2][3] * s0));
    double J33 = fma( M[2][0], s3, fma(-M[2][1], s1,  M[2][2] * s0));

    // two adjugate applications, exact pow2 renorm after each (range control)
#pragma unroll
    for (int it = 0; it < 2; it++) {
        double y0 = fma(J00, x[0], fma(J01, x[1], fma(J02, x[2], J03 * x[3])));
        double y1 = fma(J01, x[0], fma(J11, x[1], fma(J12, x[2], J13 * x[3])));
        double y2 = fma(J02, x[0], fma(J12, x[1], fma(J22, x[2], J23 * x[3])));
        double y3 = fma(J03, x[0], fma(J13, x[1], fma(J23, x[2], J33 * x[3])));
        double n2 = fma(y0, y0, fma(y1, y1, fma(y2, y2, y3 * y3)));
        double sc = pow2_inv_sqrt_approx(n2);   // ||x|| -> ~[0.5, 2]
        x[0] = y0 * sc; x[1] = y1 * sc; x[2] = y2 * sc; x[3] = y3 * sc;
    }

    // kp_3d = x[:3]/x[3]  (ratio is normalization- and sign-invariant)
    double inv = fast_drcp(x[3]);
    float* kp3 = out + OFF_KP3D + tidx * 3;
    kp3[0] = (float)(x[0] * inv);
    kp3[1] = (float)(x[1] * inv);
    kp3[2] = (float)(x[2] * inv);

    // res = sum_n |A[n,:] . (x/||x||)| = (sum_n |A[n,:].x|) * 1/||x||
    // (dot products overlap the rsqrt chain; one multiply at the end)
    double acc = 0.0;
#pragma unroll
    for (int n = 0; n < 12; n++) {
        double dsum = fma((double)Af[n][0], x[0],
                      fma((double)Af[n][1], x[1],
                      fma((double)Af[n][2], x[2], (double)Af[n][3] * x[3])));
        acc += fabs(dsum);
    }
    double nrm2 = fma(x[0], x[0], fma(x[1], x[1], fma(x[2], x[2], x[3] * x[3])));
    out[OFF_RES + tidx] = (float)(acc * fast_drsqrt(nrm2));
}

// ---------------------------------------------------------------------------
extern "C" void kernel_launch(void* const* d_in, const int* in_sizes, int n_in,
                              void* d_out, int out_size)
{
    const float* heatmap = (const float*)d_in[0];  // (384, 20, 64, 64)
    const float* proj    = (const float*)d_in[1];  // (64, 6, 3, 4)
    const float* confid  = (const float*)d_in[2];  // (384, 20)
    float* out = (float*)d_out;                    // 51200 floats

    softargmax_kernel<<<NMAPS, 256>>>(heatmap, out);
    triangulate_kernel<<<(BS * NJ + 31) / 32, 32>>>(proj, confid, out);
}

// round 10
// speedup vs baseline: 1.1544x; 1.0008x over previous
#include <cuda_runtime.h>
#include <math.h>

#define BS 64
#define NUM_CAMS 6
#define NJ 20
#define NPIX 4096          // 64*64
#define NMAPS (BS*NUM_CAMS*NJ)   // 7680

// Output layout (tuple order, flattened):
//   kp_3d : (BS, NJ, 3)            -> 3840
//   res   : (BS, NJ)               -> 1280
//   kpc   : (BS, NUM_CAMS, NJ, 3)  -> 23040
//   kph   : (BS, NUM_CAMS, NJ, 3)  -> 23040
#define OFF_KP3D 0
#define OFF_RES  (BS*NJ*3)                     // 3840
#define OFF_KPC  (OFF_RES + BS*NJ)             // 5120
#define OFF_KPH  (OFF_KPC + BS*NUM_CAMS*NJ*3)  // 28160

// ---------------------------------------------------------------------------
// Kernel 1: per-(cam-batch, joint) soft-argmax over 64x64 heatmap.
// ---------------------------------------------------------------------------
__global__ __launch_bounds__(256)
void softargmax_kernel(const float* __restrict__ hm, float* __restrict__ out)
{
    const int map = blockIdx.x;                 // 0..7679
    const float* p = hm + (size_t)map * NPIX;
    const int t = threadIdx.x;

    float vals[16];
    float lmax = -1e30f;
#pragma unroll
    for (int i = 0; i < 4; i++) {
        float4 v = __ldcs(reinterpret_cast<const float4*>(p) + i * 256 + t);
        vals[i*4+0] = v.x * 100.0f;
        vals[i*4+1] = v.y * 100.0f;
        vals[i*4+2] = v.z * 100.0f;
        vals[i*4+3] = v.w * 100.0f;
        lmax = fmaxf(lmax, fmaxf(fmaxf(vals[i*4+0], vals[i*4+1]),
                                 fmaxf(vals[i*4+2], vals[i*4+3])));
    }

    __shared__ float smax[8];
    __shared__ float sacc[3][8];

    const int wid  = t >> 5;
    const int lane = t & 31;

#pragma unroll
    for (int o = 16; o > 0; o >>= 1)
        lmax = fmaxf(lmax, __shfl_xor_sync(0xffffffffu, lmax, o));
    if (lane == 0) smax[wid] = lmax;
    __syncthreads();
    float m;
    {
        float v0 = smax[0];
#pragma unroll
        for (int w = 1; w < 8; w++) v0 = fmaxf(v0, smax[w]);
        m = v0;
    }

    // exp + weighted sums. expf(x) == 0 exactly for x < ~-104, so skipping
    // those terms matches the reference bit-for-bit (mod summation order).
    float s = 0.f, sx = 0.f, sy = 0.f;
#pragma unroll
    for (int i = 0; i < 4; i++) {
#pragma unroll
        for (int u = 0; u < 4; u++) {
            float d = vals[i*4+u] - m;
            if (__ballot_sync(0xffffffffu, d > -104.0f)) {
                if (d > -104.0f) {
                    float e = expf(d);
                    int idx = i * 1024 + t * 4 + u;   // linear pixel index
                    s  += e;
                    sx += e * (float)(idx & 63);      // column (x)
                    sy += e * (float)(idx >> 6);      // row (y)
                }
            }
        }
    }

#pragma unroll
    for (int o = 16; o > 0; o >>= 1) {
        s  += __shfl_xor_sync(0xffffffffu, s,  o);
        sx += __shfl_xor_sync(0xffffffffu, sx, o);
        sy += __shfl_xor_sync(0xffffffffu, sy, o);
    }
    if (lane == 0) { sacc[0][wid] = s; sacc[1][wid] = sx; sacc[2][wid] = sy; }
    __syncthreads();

    if (t == 0) {
        float S = 0.f, X = 0.f, Y = 0.f;
#pragma unroll
        for (int w = 0; w < 8; w++) { S += sacc[0][w]; X += sacc[1][w]; Y += sacc[2][w]; }
        float recS = 1.0f / S;        // == max(softmax) (peak term is exp(0)=1)
        float x = X * recS;
        float y = Y * recS;
        float* kph = out + OFF_KPH + map * 3;
        float* kpc = out + OFF_KPC + map * 3;
        kph[0] = x;        kph[1] = y;        kph[2] = recS;
        kpc[0] = x * 4.0f; kpc[1] = y * 4.0f; kpc[2] = recS;   // 256/64 = 4
    }
}

// ---------------------------------------------------------------------------
// fp64 helpers (float-seeded Newton; operands guaranteed float-range by callers)
// ---------------------------------------------------------------------------
__device__ __forceinline__ double fast_drcp(double d)        // ~2^-48 rel
{
    double r = (double)__frcp_rn((float)d);
    r = r * (2.0 - d * r);
    return r;
}

__device__ __forceinline__ double fast_drsqrt(double d)      // ~2^-48 rel
{
    double r = (double)__frsqrt_rn((float)d);
    r = r * (1.5 - 0.5 * d * r * r);
    r = r * (1.5 - 0.5 * d * r * r);
    return r;
}

// exact power-of-two ~ 1/sqrt(d): zero rounding perturbation, full fp64 range.
__device__ __forceinline__ double pow2_inv_sqrt_approx(double d)
{
    int hi = __double2hiint(d);
    int e  = ((hi >> 20) & 0x7ff) - 1023;   // floor(log2 d)
    int k  = -(e >> 1);                     // ~ -e/2 (within 1)
    return __hiloint2double((1023 + k) << 20, 0);
}

// ---------------------------------------------------------------------------
// Paired Jacobi rotations in COMMUTING (disjoint) planes (P,Q) and (R,S),
// {P,Q,R,S} = {0,1,2,3}. Angles are both computed from the current M (each
// rotation leaves the other's plane entries untouched), then the exact
// composition is applied in one pass. Branchless: degenerate planes get the
// exact identity (t=0, c=1, s=0). Two independent MUFU chains -> ILP 2.
// Same rotations as the R7/R9 cancellation-free t-form.
// ---------------------------------------------------------------------------
template<int P, int Q, int R, int S>
__device__ __forceinline__ void jrot_pair(float M[4][4], float V[4][4])
{
    float apq = M[P][Q],            ars = M[R][S];
    float u1  = M[Q][Q] - M[P][P],  u2  = M[S][S] - M[R][R];
    float w1  = 2.0f * apq,         w2  = 2.0f * ars;
    float z1  = fmaf(u1, u1, w1*w1), z2 = fmaf(u2, u2, w2*w2);

    float rho1 = z1 * rsqrtf(z1);   // sqrt(z1); NaN if z1==0 (masked below)
    float rho2 = z2 * rsqrtf(z2);
    float tm1  = __fdividef(w1, fabsf(u1) + rho1);
    float tm2  = __fdividef(w2, fabsf(u2) + rho2);
    float t1   = (z1 > 1e-30f) ? ((u1 >= 0.0f) ? tm1 : -tm1) : 0.0f;
    float t2   = (z2 > 1e-30f) ? ((u2 >= 0.0f) ? tm2 : -tm2) : 0.0f;
    float c1   = rsqrtf(fmaf(t1, t1, 1.0f));    // ==1.0f exactly when t1==0
    float c2   = rsqrtf(fmaf(t2, t2, 1.0f));
    float s1   = t1 * c1;
    float s2   = t2 * c2;

    // in-plane diagonal updates (exact tau-form identities)
    M[P][P] = fmaf(-t1, apq, M[P][P]);
    M[Q][Q] = fmaf( t1, apq, M[Q][Q]);
    M[R][R] = fmaf(-t2, ars, M[R][R]);
    M[S][S] = fmaf( t2, ars, M[S][S]);
    M[P][Q] = 0.0f; M[Q][P] = 0.0f;
    M[R][S] = 0.0f; M[S][R] = 0.0f;

    // cross block: rows {P,Q} x cols {R,S}; apply R1 then R2 (they commute)
    float bpr = M[P][R], bps = M[P][S], bqr = M[Q][R], bqs = M[Q][S];
    float upr = c1 * bpr - s1 * bqr;
    float uqr = s1 * bpr + c1 * bqr;
    float ups = c1 * bps - s1 * bqs;
    float uqs = s1 * bps + c1 * bqs;
    float npr = c2 * upr - s2 * ups;
    float nps = s2 * upr + c2 * ups;
    float nqr = c2 * uqr - s2 * uqs;
    float nqs = s2 * uqr + c2 * uqs;
    M[P][R] = npr; M[R][P] = npr;  M[P][S] = nps; M[S][P] = nps;
    M[Q][R] = nqr; M[R][Q] = nqr;  M[Q][S] = nqs; M[S][Q] = nqs;

    // eigenvector columns: col pair (P,Q) by R1, col pair (R,S) by R2
#pragma unroll
    for (int r = 0; r < 4; r++) {
        float vp = V[r][P], vq = V[r][Q];
        V[r][P] = c1 * vp - s1 * vq;
        V[r][Q] = s1 * vp + c1 * vq;
        float vr = V[r][R], vs = V[r][S];
        V[r][R] = c2 * vr - s2 * vs;
        V[r][S] = s2 * vr + c2 * vs;
    }
}

__global__ __launch_bounds__(32)
void triangulate_kernel(const float* __restrict__ proj,
                        const float* __restrict__ confid,
                        float* __restrict__ out)
{
    const int tidx = blockIdx.x * blockDim.x + threadIdx.x;
    if (tidx >= BS * NJ) return;
    const int b = tidx / NJ;
    const int j = tidx % NJ;

    // normalized per-camera confidences
    float cf[NUM_CAMS];
    float csum = 0.f;
#pragma unroll
    for (int c = 0; c < NUM_CAMS; c++) {
        cf[c] = confid[(b * NUM_CAMS + c) * NJ + j];
        csum += cf[c];
    }
#pragma unroll
    for (int c = 0; c < NUM_CAMS; c++) cf[c] = cf[c] / csum + 1e-5f;

    // Build A (12x4) in fp32 exactly like the reference (proj via float4)
    const float* kpc = out + OFF_KPC;
    float Af[12][4];
#pragma unroll
    for (int c = 0; c < NUM_CAMS; c++) {
        const float4* Pc4 = reinterpret_cast<const float4*>(proj + (b * NUM_CAMS + c) * 12);
        float4 r0 = Pc4[0];   // proj rows 0
        float4 r1 = Pc4[1];   // row 1
        float4 r2 = Pc4[2];   // row 2
        const float px = kpc[((b * NUM_CAMS + c) * NJ + j) * 3 + 0];
        const float py = kpc[((b * NUM_CAMS + c) * NJ + j) * 3 + 1];
        float p0[4] = { r0.x, r0.y, r0.z, r0.w };
        float p1[4] = { r1.x, r1.y, r1.z, r1.w };
        float p2[4] = { r2.x, r2.y, r2.z, r2.w };
#pragma unroll
        for (int k = 0; k < 4; k++) {
            Af[c*2+0][k] = (p2[k] * px - p0[k]) * cf[c];
            Af[c*2+1][k] = (p2[k] * py - p1[k]) * cf[c];
        }
    }

    // ---------------- fp64 M = AtA (single build; M32 is a downcast) ------
    double M[4][4];
#pragma unroll
    for (int k = 0; k < 4; k++)
#pragma unroll
        for (int l = 0; l < 4; l++) M[k][l] = 0.0;
#pragma unroll
    for (int n = 0; n < 12; n++) {
#pragma unroll
        for (int k = 0; k < 4; k++) {
            double ak = (double)Af[n][k];
#pragma unroll
            for (int l = k; l < 4; l++)
                M[k][l] = fma(ak, (double)Af[n][l], M[k][l]);
        }
    }
#pragma unroll
    for (int k = 0; k < 4; k++)
#pragma unroll
        for (int l = 0; l < k; l++) M[k][l] = M[l][k];

    // ---------------- fp32 Jacobi (paired commuting rotations) ------------
    float M32[4][4], V32[4][4];
#pragma unroll
    for (int k = 0; k < 4; k++)
#pragma unroll
        for (int l = 0; l < 4; l++) {
            M32[k][l] = (float)M[k][l];
            V32[k][l] = (k == l) ? 1.0f : 0.0f;
        }

#pragma unroll
    for (int sweep = 0; sweep < 5; sweep++) {
        jrot_pair<0,1,2,3>(M32, V32);
        jrot_pair<0,2,1,3>(M32, V32);
        jrot_pair<0,3,1,2>(M32, V32);
    }

    // seed selection: fp32 diagonal argmin (R2/R7/R9-proven)
    int mi = 0; float dmf = M32[0][0];
    if (M32[1][1] < dmf) { dmf = M32[1][1]; mi = 1; }
    if (M32[2][2] < dmf) { dmf = M32[2][2]; mi = 2; }
    if (M32[3][3] < dmf) { dmf = M32[3][3]; mi = 3; }

    double x[4];
#pragma unroll
    for (int r = 0; r < 4; r++) {
        float vr = (mi == 0) ? V32[r][0] : (mi == 1) ? V32[r][1]
                 : (mi == 2) ? V32[r][2] : V32[r][3];
        x[r] = (double)vr;
    }

    // ---------------- adjugate of symmetric 4x4 M (2x2-subdet form) -------
    double s0 = fma(M[0][0], M[1][1], -M[1][0] * M[0][1]);
    double s1 = fma(M[0][0], M[1][2], -M[1][0] * M[0][2]);
    double s2 = fma(M[0][0], M[1][3], -M[1][0] * M[0][3]);
    double s3 = fma(M[0][1], M[1][2], -M[1][1] * M[0][2]);
    double s4 = fma(M[0][1], M[1][3], -M[1][1] * M[0][3]);
    double s5 = fma(M[0][2], M[1][3], -M[1][2] * M[0][3]);
    double c5 = fma(M[2][2], M[3][3], -M[3][2] * M[2][3]);
    double c4 = fma(M[2][1], M[3][3], -M[3][1] * M[2][3]);
    double c3 = fma(M[2][1], M[3][2], -M[3][1] * M[2][2]);
    double c2 = fma(M[2][0], M[3][3], -M[3][0] * M[2][3]);
    double c1 = fma(M[2][0], M[3][2], -M[3][0] * M[2][2]);
    double c0 = fma(M[2][0], M[3][1], -M[3][0] * M[2][1]);

    double J00 = fma( M[1][1], c5, fma(-M[1][2], c4,  M[1][3] * c3));
    double J01 = fma(-M[0][1], c5, fma( M[0][2], c4, -M[0][3] * c3));
    double J02 = fma( M[3][1], s5, fma(-M[3][2], s4,  M[3][3] * s3));
    double J03 = fma(-M[2][1], s5, fma( M[2][2], s4, -M[2][3] * s3));
    double J11 = fma( M[0][0], c5, fma(-M[0][2], c2,  M[0][3] * c1));
    double J12 = fma(-M[3][0], s5, fma( M[3][2], s2, -M[3][3] * s1));
    double J13 = fma( M[2][0], s5, fma(-M[2][2], s2,  M[2][3] * s1));
    double J22 = fma( M[3][0], s4, fma(-M[3][1], s2,  M[3][3] * s0));
    double J23 = fma(-M[2][0], s4, fma( M[2][1], s2, -M[2][3] * s0));
    double J33 = fma( M[2][0], s3, fma(-M[2][1], s1,  M[2][2] * s0));

    // two adjugate applications, exact pow2 renorm after each (range control)
#pragma unroll
    for (int it = 0; it < 2; it++) {
        double y0 = fma(J00, x[0], fma(J01, x[1], fma(J02, x[2], J03 * x[3])));
        double y1 = fma(J01, x[0], fma(J11, x[1], fma(J12, x[2], J13 * x[3])));
        double y2 = fma(J02, x[0], fma(J12, x[1], fma(J22, x[2], J23 * x[3])));
        double y3 = fma(J03, x[0], fma(J13, x[1], fma(J23, x[2], J33 * x[3])));
        double n2 = fma(y0, y0, fma(y1, y1, fma(y2, y2, y3 * y3)));
        double sc = pow2_inv_sqrt_approx(n2);   // ||x|| -> ~[0.5, 2]
        x[0] = y0 * sc; x[1] = y1 * sc; x[2] = y2 * sc; x[3] = y3 * sc;
    }

    // kp_3d = x[:3]/x[3]  (ratio is normalization- and sign-invariant)
    double inv = fast_drcp(x[3]);
    float* kp3 = out + OFF_KP3D + tidx * 3;
    kp3[0] = (float)(x[0] * inv);
    kp3[1] = (float)(x[1] * inv);
    kp3[2] = (float)(x[2] * inv);

    // res = sum_n |A[n,:] . (x/||x||)| = (sum_n |A[n,:].x|) * 1/||x||
    double acc = 0.0;
#pragma unroll
    for (int n = 0; n < 12; n++) {
        double dsum = fma((double)Af[n][0], x[0],
                      fma((double)Af[n][1], x[1],
                      fma((double)Af[n][2], x[2], (double)Af[n][3] * x[3])));
        acc += fabs(dsum);
    }
    double nrm2 = fma(x[0], x[0], fma(x[1], x[1], fma(x[2], x[2], x[3] * x[3])));
    out[OFF_RES + tidx] = (float)(acc * fast_drsqrt(nrm2));
}

// ---------------------------------------------------------------------------
extern "C" void kernel_launch(void* const* d_in, const int* in_sizes, int n_in,
                              void* d_out, int out_size)
{
    const float* heatmap = (const float*)d_in[0];  // (384, 20, 64, 64)
    const float* proj    = (const float*)d_in[1];  // (64, 6, 3, 4)
    const float* confid  = (const float*)d_in[2];  // (384, 20)
    float* out = (float*)d_out;                    // 51200 floats

    softargmax_kernel<<<NMAPS, 256>>>(heatmap, out);
    triangulate_kernel<<<(BS * NJ + 31) / 32, 32>>>(proj, confid, out);
}